// round 3
// baseline (speedup 1.0000x reference)
#include <cuda_runtime.h>
#include <cuda_bf16.h>
#include <cstdint>

// ---------------------------------------------------------------------------
// Shapes (fixed by the bench)
// ---------------------------------------------------------------------------
#define BATCH 16
#define TLEN  2048
#define CDIM  200
#define DDIM  2048
#define KTOT  (BATCH * TLEN)   // 32768
#define CPAD  256              // classes padded to 16x m16 tiles

// GEMM tiling — fp8 (e4m3) mma.sync path, family-portable on sm_103
#define KC       128                    // k-bytes per smem chunk (SW128 row)
#define NTILE    128                    // d columns per CTA
#define KSPLIT   8
#define KPERCTA  (KTOT / KSPLIT)        // 4096
#define NCHUNKS  (KPERCTA / KC)         // 32

// smem: A 2 x 32KB (256 rows x 128B), B 2 x 16KB (128 rows x 128B)
#define SM_A0 0
#define SM_A1 32768
#define SM_B0 65536
#define SM_B1 (65536 + 16384)
#define SMEM_BYTES (65536 + 32768)      // 98304

#define E4M3_ONE 0x38                   // 1.0 in e4m3

// ---------------------------------------------------------------------------
// Scratch (device globals: allocation-free per harness rules)
// ---------------------------------------------------------------------------
__device__ __align__(128) uint8_t g_Amat[(size_t)CPAD * KTOT];  // 8 MB e4m3 mask
__device__ float g_sums[CPAD * DDIM];                            // 2 MB
__device__ int   g_counts[CPAD];

// ---------------------------------------------------------------------------
// helpers
// ---------------------------------------------------------------------------
__device__ __forceinline__ uint32_t smem_u32(const void* p) {
    uint32_t a;
    asm("{ .reg .u64 t; cvta.to.shared.u64 t, %1; cvt.u32.u64 %0, t; }"
        : "=r"(a) : "l"(p));
    return a;
}
__device__ __forceinline__ uint32_t sw128(uint32_t off) {
    return off ^ ((off >> 3) & 0x70);
}
__device__ __forceinline__ void sts128(uint32_t a, uint32_t x, uint32_t y,
                                       uint32_t z, uint32_t w) {
    asm volatile("st.shared.v4.b32 [%0], {%1,%2,%3,%4};"
                 :: "r"(a), "r"(x), "r"(y), "r"(z), "r"(w) : "memory");
}
// d = { cvt(hi) << 8 | cvt(lo) }
__device__ __forceinline__ uint32_t cvt_e4m3x2(float hi, float lo) {
    uint16_t r;
    asm("cvt.rn.satfinite.e4m3x2.f32 %0, %1, %2;" : "=h"(r) : "f"(hi), "f"(lo));
    return (uint32_t)r;
}
__device__ __forceinline__ void cp_async16(uint32_t saddr, const void* gaddr) {
    asm volatile("cp.async.cg.shared.global [%0], [%1], 16;"
                 :: "r"(saddr), "l"(gaddr) : "memory");
}
__device__ __forceinline__ void cp_commit() {
    asm volatile("cp.async.commit_group;" ::: "memory");
}
__device__ __forceinline__ void cp_wait0() {
    asm volatile("cp.async.wait_group 0;" ::: "memory");
}
__device__ __forceinline__ void ldmatrix_x4(uint32_t* r, uint32_t addr) {
    asm volatile("ldmatrix.sync.aligned.m8n8.x4.shared.b16 {%0,%1,%2,%3}, [%4];"
                 : "=r"(r[0]), "=r"(r[1]), "=r"(r[2]), "=r"(r[3]) : "r"(addr));
}
// fp8 e4m3 MMA: D[16x8] += A[16x32] * B[32x8], f32 accumulate
__device__ __forceinline__ void mma16832(float* c, const uint32_t* a,
                                         uint32_t b0, uint32_t b1) {
    asm volatile(
        "mma.sync.aligned.m16n8k32.row.col.f32.e4m3.e4m3.f32 "
        "{%0,%1,%2,%3}, {%4,%5,%6,%7}, {%8,%9}, {%0,%1,%2,%3};"
        : "+f"(c[0]), "+f"(c[1]), "+f"(c[2]), "+f"(c[3])
        : "r"(a[0]), "r"(a[1]), "r"(a[2]), "r"(a[3]), "r"(b0), "r"(b1));
}

// ---------------------------------------------------------------------------
// Stage 0: zero scratch (graph replays reuse globals)
// ---------------------------------------------------------------------------
__global__ void zero_kernel() {
    int i = blockIdx.x * 256 + threadIdx.x;
    if (i < CPAD * DDIM) g_sums[i] = 0.0f;
    if (i < CPAD) g_counts[i] = 0;
}

// ---------------------------------------------------------------------------
// Stage 1: e4m3 mask matrix Amat[256][32768] (K-major) + per-class counts.
// Block = 64 consecutive bt for all 256 classes; smem transpose keeps both
// the act reads and the Amat writes coalesced.
// ---------------------------------------------------------------------------
__global__ __launch_bounds__(256) void build_mask_kernel(
    const int* __restrict__ act, const int* __restrict__ vid) {
    __shared__ uint8_t m[CPAD][72];
    __shared__ int vids[CPAD];

    int tid = threadIdx.x;
    int bt0 = blockIdx.x * 64;
    int b = bt0 >> 11;  // T = 2048

    for (int c = tid; c < CPAD; c += 256)
        vids[c] = (c < CDIM) ? vid[b * CDIM + c] : 0;
    __syncthreads();

    for (int idx = tid; idx < 64 * CDIM; idx += 256) {
        int r = idx / CDIM, c = idx - r * CDIM;
        int a = act[(size_t)(bt0 + r) * CDIM + c];
        m[c][r] = (a != 0 && vids[c] != 0) ? (uint8_t)E4M3_ONE : (uint8_t)0;
    }
    for (int idx = tid; idx < (CPAD - CDIM) * 64; idx += 256)
        m[CDIM + (idx >> 6)][idx & 63] = 0;
    __syncthreads();

    int lid = tid & 31, wid = tid >> 5;
    for (int c = wid; c < CPAD; c += 8) {
        uint16_t v = *(const uint16_t*)&m[c][2 * lid];
        *(uint16_t*)(g_Amat + (size_t)c * KTOT + bt0 + 2 * lid) = v;
        int cnt = (int)((v & 0xFFu) != 0) + (int)((v >> 8) != 0);
        cnt = __reduce_add_sync(0xFFFFFFFFu, cnt);
        if (lid == 0 && c < CDIM && cnt) atomicAdd(&g_counts[c], cnt);
    }
}

// ---------------------------------------------------------------------------
// Stage 2: fp8 mma.sync GEMM  sums[c,d] += sum_k mask[c,k] * feats[k,d]
// CTA: M=256 x N=128, 16 warps (4x4), warp tile 64x32, double-buffered KC=128.
// ---------------------------------------------------------------------------
__global__ __launch_bounds__(512, 1) void gemm_kernel(const float* __restrict__ feats) {
    extern __shared__ char smem[];
    const uint32_t sb = smem_u32(smem);
    const int tid = threadIdx.x;
    const int lane = tid & 31, wid = tid >> 5;
    const int wm = wid & 3;        // m block: wm*64
    const int wn = wid >> 2;       // n block: wn*32
    const int d0 = blockIdx.x * NTILE;
    const int kbase = blockIdx.y * KPERCTA;

    // B-load addressing: thread -> (d column, k quarter of 32)
    const int dcol = tid & 127;
    const int kq = tid >> 7;       // 0..3, covers k = kq*32 .. +31

    float acc[4][4][4];
#pragma unroll
    for (int i = 0; i < 4; i++)
#pragma unroll
        for (int j = 0; j < 4; j++)
#pragma unroll
            for (int r = 0; r < 4; r++) acc[i][j][r] = 0.0f;

    // ldmatrix per-lane offsets (pre-swizzle); byte columns, 128B rows
    uint32_t a_off[4];
#pragma unroll
    for (int mt = 0; mt < 4; mt++) {
        int rowA = wm * 64 + mt * 16 + (lane & 15);
        a_off[mt] = (uint32_t)(rowA * 128 + (lane >> 4) * 16);
    }
    uint32_t b_off[2];
#pragma unroll
    for (int np = 0; np < 2; np++) {
        int rowB = wn * 32 + np * 16 + ((lane >> 4) << 3) + (lane & 7);
        b_off[np] = (uint32_t)(rowB * 128 + ((lane >> 3) & 1) * 16);
    }

    uint32_t pb[8];  // converted e4m3 B data: 32 k-bytes for this thread's d col

    // ---- load chunk ck: A via cp.async, B f32 -> e4m3 into pb ----
    auto issue_loads = [&](int ck, int s) {
        const int k0 = kbase + ck * KC;
        const uint32_t abase = sb + (s ? SM_A1 : SM_A0);
#pragma unroll
        for (int it = 0; it < 4; it++) {
            int idx = it * 512 + tid;
            int c = idx >> 3, seg = idx & 7;
            const void* g = g_Amat + (size_t)c * KTOT + k0 + seg * 16;
            cp_async16(abase + sw128((uint32_t)(c * 128 + seg * 16)), g);
        }
        cp_commit();
        const float* fp = feats + (size_t)(k0 + kq * 32) * DDIM + d0 + dcol;
        float f[32];
#pragma unroll
        for (int j = 0; j < 32; j++) f[j] = fp[(size_t)j * DDIM];  // coalesced
#pragma unroll
        for (int j = 0; j < 8; j++) {
            uint32_t lo = cvt_e4m3x2(f[4 * j + 1], f[4 * j]);
            uint32_t hi = cvt_e4m3x2(f[4 * j + 3], f[4 * j + 2]);
            pb[j] = lo | (hi << 16);
        }
    };
    // ---- store converted B tile to stage s ----
    auto store_b = [&](int s) {
        const uint32_t bbase = sb + (s ? SM_B1 : SM_B0);
        uint32_t o0 = (uint32_t)(dcol * 128 + kq * 32);
        sts128(bbase + sw128(o0), pb[0], pb[1], pb[2], pb[3]);
        sts128(bbase + sw128(o0 + 16), pb[4], pb[5], pb[6], pb[7]);
    };
    // ---- compute on stage s (KC=128 k-bytes, 4 mma-ksteps of 32) ----
    auto compute = [&](int s) {
        const uint32_t abase = sb + (s ? SM_A1 : SM_A0);
        const uint32_t bbase = sb + (s ? SM_B1 : SM_B0);
#pragma unroll
        for (int ks = 0; ks < 4; ks++) {
            uint32_t a[4][4], b[2][4];
#pragma unroll
            for (int mt = 0; mt < 4; mt++)
                ldmatrix_x4(a[mt], abase + sw128(a_off[mt] + ks * 32));
#pragma unroll
            for (int np = 0; np < 2; np++)
                ldmatrix_x4(b[np], bbase + sw128(b_off[np] + ks * 32));
#pragma unroll
            for (int mt = 0; mt < 4; mt++)
#pragma unroll
                for (int nt = 0; nt < 4; nt++)
                    mma16832(acc[mt][nt], a[mt],
                             b[nt >> 1][(nt & 1) * 2], b[nt >> 1][(nt & 1) * 2 + 1]);
        }
    };

    // prologue
    issue_loads(0, 0);
    cp_wait0();
    store_b(0);
    __syncthreads();

#pragma unroll 1
    for (int ck = 0; ck < NCHUNKS; ck++) {
        const int s = ck & 1;
        if (ck + 1 < NCHUNKS) issue_loads(ck + 1, s ^ 1);
        compute(s);
        if (ck + 1 < NCHUNKS) {
            store_b(s ^ 1);
            cp_wait0();
            __syncthreads();
        }
    }

    // epilogue: atomic accumulate into global partial sums
    const int row = lane >> 2;
    const int col = (lane & 3) * 2;
#pragma unroll
    for (int mt = 0; mt < 4; mt++) {
#pragma unroll
        for (int nt = 0; nt < 4; nt++) {
            int cls = wm * 64 + mt * 16 + row;
            int dd = d0 + wn * 32 + nt * 8 + col;
            float* gp = g_sums + (size_t)cls * DDIM + dd;
            atomicAdd(gp, acc[mt][nt][0]);
            atomicAdd(gp + 1, acc[mt][nt][1]);
            float* gp2 = gp + 8 * DDIM;
            atomicAdd(gp2, acc[mt][nt][2]);
            atomicAdd(gp2 + 1, acc[mt][nt][3]);
        }
    }
}

// ---------------------------------------------------------------------------
// Stage 3: momentum update (vectorized)
// ---------------------------------------------------------------------------
__global__ void finalize_kernel(const float4* __restrict__ proto,
                                float4* __restrict__ out) {
    int i = blockIdx.x * 256 + threadIdx.x;
    if (i >= CDIM * DDIM / 4) return;
    int c = i >> 9;  // (4*i) / 2048
    float4 p = proto[i];
    int cnt = g_counts[c];
    const float4 s = ((const float4*)g_sums)[i];
    float inv = 0.001f / fmaxf((float)cnt, 1.0f);
    float4 r;
    r.x = 0.999f * p.x + s.x * inv;
    r.y = 0.999f * p.y + s.y * inv;
    r.z = 0.999f * p.z + s.z * inv;
    r.w = 0.999f * p.w + s.w * inv;
    out[i] = (cnt > 0) ? r : p;
}

// ---------------------------------------------------------------------------
// Launch
// ---------------------------------------------------------------------------
extern "C" void kernel_launch(void* const* d_in, const int* in_sizes, int n_in,
                              void* d_out, int out_size) {
    const float* feats = (const float*)d_in[0];
    const int* act = (const int*)d_in[1];
    const int* vid = (const int*)d_in[2];
    const float* proto = (const float*)d_in[3];
    float* out = (float*)d_out;

    cudaFuncSetAttribute(gemm_kernel, cudaFuncAttributeMaxDynamicSharedMemorySize,
                         SMEM_BYTES);

    zero_kernel<<<(CPAD * DDIM + 255) / 256, 256>>>();
    build_mask_kernel<<<KTOT / 64, 256>>>(act, vid);
    gemm_kernel<<<dim3(DDIM / NTILE, KSPLIT), 512, SMEM_BYTES>>>(feats);
    finalize_kernel<<<(CDIM * DDIM / 4 + 255) / 256, 256>>>(
        (const float4*)proto, (float4*)out);
}

// round 5
// speedup vs baseline: 1.3257x; 1.3257x over previous
#include <cuda_runtime.h>
#include <cuda_bf16.h>
#include <cstdint>

// ---------------------------------------------------------------------------
// Shapes (fixed by the bench)
// ---------------------------------------------------------------------------
#define BATCH 16
#define TLEN  2048
#define CDIM  200
#define DDIM  2048
#define MPAD  256              // compacted class rows per batch (padded)

// GEMM tiling: per-batch compacted bf16 mma.sync
#define KC      64             // k per smem chunk (64 bf16 = 128B SW128 row)
#define NTILE   128            // d columns per CTA
#define NCHUNKS (TLEN / KC)    // 32

// smem: A 2 x 16KB (128 rows x 128B), B 2 x 16KB
#define SM_A0 0
#define SM_A1 16384
#define SM_B0 32768
#define SM_B1 (32768 + 16384)
#define SMEM_BYTES 65536

// ---------------------------------------------------------------------------
// Scratch — device symbols ONLY, never passed from host (ATS shadow trap!)
// ---------------------------------------------------------------------------
__device__ __align__(128) __nv_bfloat16 g_Amat[(size_t)BATCH * MPAD * TLEN]; // 16MB
__device__ float g_sums[MPAD * DDIM];   // indexed by TRUE class (0..199)
__device__ int   g_counts[MPAD];
__device__ int   g_clist[BATCH * MPAD]; // compact j -> true class c
__device__ int   g_cmap[BATCH * MPAD];  // true class c -> compact j (or -1)
__device__ int   g_nact[BATCH];

// ---------------------------------------------------------------------------
// helpers
// ---------------------------------------------------------------------------
__device__ __forceinline__ uint32_t smem_u32(const void* p) {
    uint32_t a;
    asm("{ .reg .u64 t; cvta.to.shared.u64 t, %1; cvt.u32.u64 %0, t; }"
        : "=r"(a) : "l"(p));
    return a;
}
__device__ __forceinline__ uint32_t sw128(uint32_t off) {
    return off ^ ((off >> 3) & 0x70);
}
__device__ __forceinline__ void sts128(uint32_t a, uint32_t x, uint32_t y,
                                       uint32_t z, uint32_t w) {
    asm volatile("st.shared.v4.b32 [%0], {%1,%2,%3,%4};"
                 :: "r"(a), "r"(x), "r"(y), "r"(z), "r"(w) : "memory");
}
__device__ __forceinline__ uint32_t pack_bf16x2(float lo, float hi) {
    uint32_t r;
    asm("cvt.rn.satfinite.bf16x2.f32 %0, %1, %2;" : "=r"(r) : "f"(hi), "f"(lo));
    return r;
}
__device__ __forceinline__ void cp_async16(uint32_t saddr, const void* gaddr) {
    asm volatile("cp.async.cg.shared.global [%0], [%1], 16;"
                 :: "r"(saddr), "l"(gaddr) : "memory");
}
__device__ __forceinline__ void cp_commit() {
    asm volatile("cp.async.commit_group;" ::: "memory");
}
__device__ __forceinline__ void cp_wait0() {
    asm volatile("cp.async.wait_group 0;" ::: "memory");
}
__device__ __forceinline__ void ldmatrix_x4(uint32_t* r, uint32_t addr) {
    asm volatile("ldmatrix.sync.aligned.m8n8.x4.shared.b16 {%0,%1,%2,%3}, [%4];"
                 : "=r"(r[0]), "=r"(r[1]), "=r"(r[2]), "=r"(r[3]) : "r"(addr));
}
__device__ __forceinline__ void mma16816(float* c, const uint32_t* a,
                                         uint32_t b0, uint32_t b1) {
    asm volatile(
        "mma.sync.aligned.m16n8k16.row.col.f32.bf16.bf16.f32 "
        "{%0,%1,%2,%3}, {%4,%5,%6,%7}, {%8,%9}, {%0,%1,%2,%3};"
        : "+f"(c[0]), "+f"(c[1]), "+f"(c[2]), "+f"(c[3])
        : "r"(a[0]), "r"(a[1]), "r"(a[2]), "r"(a[3]), "r"(b0), "r"(b1));
}

// ---------------------------------------------------------------------------
// Stage 0: zero scratch (Amat + sums + counts); replay-safe
// ---------------------------------------------------------------------------
#define AMAT_U4 ((size_t)BATCH * MPAD * TLEN * 2 / 16)   // 1,048,576
#define SUMS_U4 (MPAD * DDIM * 4 / 16)                   // 131,072
__global__ void zero_kernel() {
    size_t i = (size_t)blockIdx.x * 256 + threadIdx.x;
    const uint4 z = {0, 0, 0, 0};
    if (i < AMAT_U4) ((uint4*)g_Amat)[i] = z;
    else if (i < AMAT_U4 + SUMS_U4) ((uint4*)g_sums)[i - AMAT_U4] = z;
    if (i < MPAD) g_counts[i] = 0;
}

// ---------------------------------------------------------------------------
// Stage 1a: per-batch active-class compaction (g_cmap/g_clist/g_nact)
// ---------------------------------------------------------------------------
__global__ __launch_bounds__(256) void prep_kernel(const int* __restrict__ vid) {
    __shared__ int warp_sums[8];
    __shared__ int warp_base[8];
    int b = blockIdx.x, tid = threadIdx.x;
    int lid = tid & 31, wid = tid >> 5;

    int flag = (tid < CDIM) ? (vid[b * CDIM + tid] != 0) : 0;
    uint32_t bal = __ballot_sync(0xFFFFFFFFu, flag);
    if (lid == 0) warp_sums[wid] = __popc(bal);
    __syncthreads();
    if (tid == 0) {
        int run = 0;
        for (int w = 0; w < 8; w++) { warp_base[w] = run; run += warp_sums[w]; }
        g_nact[b] = run;
    }
    __syncthreads();
    int j = warp_base[wid] + __popc(bal & ((1u << lid) - 1));
    if (flag) {
        g_cmap[b * MPAD + tid] = j;
        g_clist[b * MPAD + j] = tid;
    } else {
        g_cmap[b * MPAD + tid] = -1;
    }
}

// ---------------------------------------------------------------------------
// Stage 1b: compacted bf16 mask Amat[b][j][t] + per-class counts.
// Block = 64 consecutive t of one batch; smem transpose for coalescing.
// m[] is fully zero-initialized first so no uninitialized smem can ever
// reach the GEMM operand.
// ---------------------------------------------------------------------------
__global__ __launch_bounds__(256) void build_mask_kernel(const int* __restrict__ act) {
    __shared__ __nv_bfloat16 m[CDIM][66];
    __shared__ int cmap_s[MPAD];
    __shared__ int clist_s[CDIM];

    int tid = threadIdx.x;
    int b = blockIdx.x >> 5;
    int t0 = (blockIdx.x & 31) * 64;
    int nact = g_nact[b];

    for (int c = tid; c < MPAD; c += 256) cmap_s[c] = g_cmap[b * MPAD + c];
    for (int j = tid; j < nact; j += 256) clist_s[j] = g_clist[b * MPAD + j];
    // zero-fill transpose buffer (CDIM*33 u32)
    for (int i = tid; i < CDIM * 33; i += 256) ((uint32_t*)m)[i] = 0;
    __syncthreads();

    const __nv_bfloat16 one = __float2bfloat16(1.0f);
    const __nv_bfloat16 zero = __float2bfloat16(0.0f);

    const int* ap = act + ((size_t)b * TLEN + t0) * CDIM;
    for (int idx = tid; idx < 64 * CDIM; idx += 256) {
        int r = idx / CDIM, c = idx - r * CDIM;
        int j = cmap_s[c];
        if (j >= 0) m[j][r] = (ap[(size_t)r * CDIM + c] != 0) ? one : zero;
    }
    __syncthreads();

    int lid = tid & 31, wid = tid >> 5;
    for (int j = wid; j < nact; j += 8) {
        uint32_t v = *(const uint32_t*)&m[j][2 * lid];
        *(uint32_t*)((char*)g_Amat +
                     ((size_t)(b * MPAD + j) * TLEN + t0 + 2 * lid) * 2) = v;
        int cnt = (int)((v & 0xFFFFu) != 0) + (int)((v >> 16) != 0);
        cnt = __reduce_add_sync(0xFFFFFFFFu, cnt);
        if (lid == 0 && cnt) atomicAdd(&g_counts[clist_s[j]], cnt);
    }
}

// ---------------------------------------------------------------------------
// Stage 2: per-batch compacted bf16 GEMM.
// grid (16 d-tiles, 16 batches, 2 m-tiles); CTA M=128 x N=128, K=2048.
// 16 warps as 8m x 2n, warp tile 16x64; warps beyond nact skip compute.
// ---------------------------------------------------------------------------
__global__ __launch_bounds__(512, 1) void gemm_kernel(const float* __restrict__ feats) {
    const int b = blockIdx.y;
    const int mbase = blockIdx.z * 128;
    const int nact = g_nact[b];
    if (mbase >= nact) return;
    const int lim = nact - mbase;       // active rows in this m-tile

    extern __shared__ char smem[];
    const uint32_t sb = smem_u32(smem);
    const int tid = threadIdx.x;
    const int lane = tid & 31, wid = tid >> 5;
    const int wm = wid & 7;             // m: wm*16
    const int wn = wid >> 3;            // n: wn*64
    const int d0 = blockIdx.x * NTILE;
    const bool wactive = (wm * 16) < lim;

    const int dcol = tid & 127;
    const int kq = tid >> 7;            // 0..3 -> k = kq*16 .. +15

    float acc[8][4];
#pragma unroll
    for (int i = 0; i < 8; i++)
#pragma unroll
        for (int r = 0; r < 4; r++) acc[i][r] = 0.0f;

    const uint32_t a_off =
        (uint32_t)((wm * 16 + (lane & 15)) * 128 + (lane >> 4) * 16);
    uint32_t b_off[4];
#pragma unroll
    for (int nb = 0; nb < 4; nb++) {
        int rowB = wn * 64 + nb * 16 + ((lane >> 4) << 3) + (lane & 7);
        b_off[nb] = (uint32_t)(rowB * 128 + ((lane >> 3) & 1) * 16);
    }

    const __nv_bfloat16* abase_g = g_Amat + (size_t)(b * MPAD + mbase) * TLEN;
    const float* fbase = feats + (size_t)b * TLEN * DDIM;

    float fst[16];

    auto issue_loads = [&](int ck, int s) {
        const int k0 = ck * KC;
        const uint32_t abase = sb + (s ? SM_A1 : SM_A0);
#pragma unroll
        for (int it = 0; it < 2; it++) {
            int idx = it * 512 + tid;
            int row = idx >> 3, seg = idx & 7;
            const void* g = abase_g + (size_t)row * TLEN + k0 + seg * 8;
            cp_async16(abase + sw128((uint32_t)(row * 128 + seg * 16)), g);
        }
        cp_commit();
        const float* fp = fbase + (size_t)(k0 + kq * 16) * DDIM + d0 + dcol;
#pragma unroll
        for (int j = 0; j < 16; j++) fst[j] = fp[(size_t)j * DDIM];
    };
    auto store_b = [&](int s) {
        const uint32_t bbase = sb + (s ? SM_B1 : SM_B0);
        uint32_t p[8];
#pragma unroll
        for (int j = 0; j < 8; j++) p[j] = pack_bf16x2(fst[2 * j], fst[2 * j + 1]);
        uint32_t o0 = (uint32_t)(dcol * 128 + kq * 32);
        sts128(bbase + sw128(o0), p[0], p[1], p[2], p[3]);
        sts128(bbase + sw128(o0 + 16), p[4], p[5], p[6], p[7]);
    };
    auto compute = [&](int s) {
        if (!wactive) return;
        const uint32_t abase = sb + (s ? SM_A1 : SM_A0);
        const uint32_t bbase = sb + (s ? SM_B1 : SM_B0);
#pragma unroll
        for (int ks = 0; ks < 4; ks++) {
            uint32_t a[4], bf[4][4];
            ldmatrix_x4(a, abase + sw128(a_off + ks * 32));
#pragma unroll
            for (int nb = 0; nb < 4; nb++)
                ldmatrix_x4(bf[nb], bbase + sw128(b_off[nb] + ks * 32));
#pragma unroll
            for (int nt = 0; nt < 8; nt++)
                mma16816(acc[nt], a,
                         bf[nt >> 1][(nt & 1) * 2], bf[nt >> 1][(nt & 1) * 2 + 1]);
        }
    };

    issue_loads(0, 0);
    cp_wait0();
    store_b(0);
    __syncthreads();

#pragma unroll 1
    for (int ck = 0; ck < NCHUNKS; ck++) {
        const int s = ck & 1;
        if (ck + 1 < NCHUNKS) issue_loads(ck + 1, s ^ 1);
        compute(s);
        if (ck + 1 < NCHUNKS) {
            store_b(s ^ 1);
            cp_wait0();
            __syncthreads();
        }
    }

    // epilogue: scatter-add compact rows to true class rows
    if (wactive) {
        const int row = lane >> 2;
        const int col = (lane & 3) * 2;
        const int j0 = mbase + wm * 16 + row;
        const int j1 = j0 + 8;
        const int c0 = (j0 < nact) ? g_clist[b * MPAD + j0] : -1;
        const int c1 = (j1 < nact) ? g_clist[b * MPAD + j1] : -1;
#pragma unroll
        for (int nt = 0; nt < 8; nt++) {
            int dd = d0 + wn * 64 + nt * 8 + col;
            if (c0 >= 0) {
                float* gp = g_sums + (size_t)c0 * DDIM + dd;
                atomicAdd(gp, acc[nt][0]);
                atomicAdd(gp + 1, acc[nt][1]);
            }
            if (c1 >= 0) {
                float* gp = g_sums + (size_t)c1 * DDIM + dd;
                atomicAdd(gp, acc[nt][2]);
                atomicAdd(gp + 1, acc[nt][3]);
            }
        }
    }
}

// ---------------------------------------------------------------------------
// Stage 3: momentum update (vectorized)
// ---------------------------------------------------------------------------
__global__ void finalize_kernel(const float4* __restrict__ proto,
                                float4* __restrict__ out) {
    int i = blockIdx.x * 256 + threadIdx.x;
    if (i >= CDIM * DDIM / 4) return;
    int c = i >> 9;
    float4 p = proto[i];
    int cnt = g_counts[c];
    const float4 s = ((const float4*)g_sums)[i];
    float inv = 0.001f / fmaxf((float)cnt, 1.0f);
    float4 r;
    r.x = 0.999f * p.x + s.x * inv;
    r.y = 0.999f * p.y + s.y * inv;
    r.z = 0.999f * p.z + s.z * inv;
    r.w = 0.999f * p.w + s.w * inv;
    out[i] = (cnt > 0) ? r : p;
}

// ---------------------------------------------------------------------------
// Launch
// ---------------------------------------------------------------------------
extern "C" void kernel_launch(void* const* d_in, const int* in_sizes, int n_in,
                              void* d_out, int out_size) {
    const float* feats = (const float*)d_in[0];
    const int* act = (const int*)d_in[1];
    const int* vid = (const int*)d_in[2];
    const float* proto = (const float*)d_in[3];
    float* out = (float*)d_out;

    cudaFuncSetAttribute(gemm_kernel, cudaFuncAttributeMaxDynamicSharedMemorySize,
                         SMEM_BYTES);

    size_t zslots = AMAT_U4 + SUMS_U4;
    zero_kernel<<<(unsigned)((zslots + 255) / 256), 256>>>();
    prep_kernel<<<BATCH, 256>>>(vid);
    build_mask_kernel<<<BATCH * (TLEN / 64), 256>>>(act);
    gemm_kernel<<<dim3(DDIM / NTILE, BATCH, 2), 512, SMEM_BYTES>>>(feats);
    finalize_kernel<<<(CDIM * DDIM / 4 + 255) / 256, 256>>>(
        (const float4*)proto, (float4*)out);
}

// round 6
// speedup vs baseline: 1.6606x; 1.2525x over previous
#include <cuda_runtime.h>
#include <cuda_bf16.h>
#include <cstdint>

// ---------------------------------------------------------------------------
// Shapes (fixed by the bench)
// ---------------------------------------------------------------------------
#define BATCH 16
#define TLEN  2048
#define CDIM  200
#define DDIM  2048
#define MPAD  256              // compacted class rows per batch (padded)

// GEMM tiling: per-batch compacted bf16 mma.sync, k-split 4
#define KC      64             // k per smem chunk (64 bf16 = 128B SW128 row)
#define NTILE   128            // d columns per CTA
#define KSPLIT  4
#define KPER    (TLEN / KSPLIT)        // 512
#define NCHUNKS (KPER / KC)            // 8

// smem: A 2 x 16KB (128 rows x 128B), B 2 x 16KB
#define SM_A0 0
#define SM_A1 16384
#define SM_B0 32768
#define SM_B1 (32768 + 16384)
#define SMEM_BYTES 65536

// ---------------------------------------------------------------------------
// Scratch — device symbols ONLY, never passed from host (ATS shadow trap!)
// ---------------------------------------------------------------------------
__device__ __align__(128) __nv_bfloat16 g_Amat[(size_t)BATCH * MPAD * TLEN]; // 16MB
__device__ float g_sums[MPAD * DDIM];   // indexed by TRUE class (0..199)
__device__ int   g_counts[MPAD];
__device__ int   g_clist[BATCH * MPAD]; // compact j -> true class c
__device__ int   g_cmap[BATCH * MPAD];  // true class c -> compact j (or -1)
__device__ int   g_nact[BATCH];

// ---------------------------------------------------------------------------
// helpers
// ---------------------------------------------------------------------------
__device__ __forceinline__ uint32_t smem_u32(const void* p) {
    uint32_t a;
    asm("{ .reg .u64 t; cvta.to.shared.u64 t, %1; cvt.u32.u64 %0, t; }"
        : "=r"(a) : "l"(p));
    return a;
}
__device__ __forceinline__ uint32_t sw128(uint32_t off) {
    return off ^ ((off >> 3) & 0x70);
}
__device__ __forceinline__ void sts128(uint32_t a, uint32_t x, uint32_t y,
                                       uint32_t z, uint32_t w) {
    asm volatile("st.shared.v4.b32 [%0], {%1,%2,%3,%4};"
                 :: "r"(a), "r"(x), "r"(y), "r"(z), "r"(w) : "memory");
}
__device__ __forceinline__ uint32_t pack_bf16x2(float lo, float hi) {
    uint32_t r;
    asm("cvt.rn.satfinite.bf16x2.f32 %0, %1, %2;" : "=r"(r) : "f"(hi), "f"(lo));
    return r;
}
__device__ __forceinline__ void cp_async16(uint32_t saddr, const void* gaddr) {
    asm volatile("cp.async.cg.shared.global [%0], [%1], 16;"
                 :: "r"(saddr), "l"(gaddr) : "memory");
}
__device__ __forceinline__ void cp_commit() {
    asm volatile("cp.async.commit_group;" ::: "memory");
}
__device__ __forceinline__ void cp_wait0() {
    asm volatile("cp.async.wait_group 0;" ::: "memory");
}
__device__ __forceinline__ void ldmatrix_x4(uint32_t* r, uint32_t addr) {
    asm volatile("ldmatrix.sync.aligned.m8n8.x4.shared.b16 {%0,%1,%2,%3}, [%4];"
                 : "=r"(r[0]), "=r"(r[1]), "=r"(r[2]), "=r"(r[3]) : "r"(addr));
}
__device__ __forceinline__ void mma16816(float* c, const uint32_t* a,
                                         uint32_t b0, uint32_t b1) {
    asm volatile(
        "mma.sync.aligned.m16n8k16.row.col.f32.bf16.bf16.f32 "
        "{%0,%1,%2,%3}, {%4,%5,%6,%7}, {%8,%9}, {%0,%1,%2,%3};"
        : "+f"(c[0]), "+f"(c[1]), "+f"(c[2]), "+f"(c[3])
        : "r"(a[0]), "r"(a[1]), "r"(a[2]), "r"(a[3]), "r"(b0), "r"(b1));
}

// ---------------------------------------------------------------------------
// Stage 0: zero sums + counts only (Amat padding rows are never consumed:
// epilogue discards rows >= nact, warp-skip avoids rows >= ceil16(lim)).
// ---------------------------------------------------------------------------
#define SUMS_U4 (MPAD * DDIM * 4 / 16)   // 131072
__global__ void zero_kernel() {
    int i = blockIdx.x * 256 + threadIdx.x;
    const uint4 z = {0, 0, 0, 0};
    if (i < SUMS_U4) ((uint4*)g_sums)[i] = z;
    if (i < MPAD) g_counts[i] = 0;
}

// ---------------------------------------------------------------------------
// Stage 1a: per-batch active-class compaction (g_cmap/g_clist/g_nact)
// ---------------------------------------------------------------------------
__global__ __launch_bounds__(256) void prep_kernel(const int* __restrict__ vid) {
    __shared__ int warp_sums[8];
    __shared__ int warp_base[8];
    int b = blockIdx.x, tid = threadIdx.x;
    int lid = tid & 31, wid = tid >> 5;

    int flag = (tid < CDIM) ? (vid[b * CDIM + tid] != 0) : 0;
    uint32_t bal = __ballot_sync(0xFFFFFFFFu, flag);
    if (lid == 0) warp_sums[wid] = __popc(bal);
    __syncthreads();
    if (tid == 0) {
        int run = 0;
        for (int w = 0; w < 8; w++) { warp_base[w] = run; run += warp_sums[w]; }
        g_nact[b] = run;
    }
    __syncthreads();
    int j = warp_base[wid] + __popc(bal & ((1u << lid) - 1));
    if (flag) {
        g_cmap[b * MPAD + tid] = j;
        g_clist[b * MPAD + j] = tid;
    } else {
        g_cmap[b * MPAD + tid] = -1;
    }
}

// ---------------------------------------------------------------------------
// Stage 1b: compacted bf16 mask Amat[b][j][t] + per-class counts.
// Thread owns one true class (register j); no division, no smem zero-fill.
// Block = 64 consecutive t of one batch; smem transpose for coalesced writes.
// ---------------------------------------------------------------------------
__global__ __launch_bounds__(256) void build_mask_kernel(const int* __restrict__ act) {
    __shared__ __nv_bfloat16 m[CDIM][66];   // only rows < nact are written/read

    int tid = threadIdx.x;
    int b = blockIdx.x >> 5;
    int t0 = (blockIdx.x & 31) * 64;
    int nact = g_nact[b];
    int j = (tid < CDIM) ? g_cmap[b * MPAD + tid] : -1;

    const __nv_bfloat16 one = __float2bfloat16(1.0f);
    const __nv_bfloat16 zero = __float2bfloat16(0.0f);

    const int* ap = act + ((size_t)b * TLEN + t0) * CDIM + tid;
    int cnt = 0;
    if (j >= 0) {
#pragma unroll 4
        for (int r = 0; r < 64; r++) {
            bool on = ap[r * CDIM] != 0;       // coalesced across lanes
            m[j][r] = on ? one : zero;
            cnt += on;
        }
        if (cnt) atomicAdd(&g_counts[tid], cnt);
    }
    __syncthreads();

    int lid = tid & 31, wid = tid >> 5;
    for (int jj = wid; jj < nact; jj += 8) {
        uint32_t v = *(const uint32_t*)&m[jj][2 * lid];
        *(uint32_t*)((char*)g_Amat +
                     ((size_t)(b * MPAD + jj) * TLEN + t0 + 2 * lid) * 2) = v;
    }
}

// ---------------------------------------------------------------------------
// Stage 2: per-batch compacted bf16 GEMM, k-split 4 for wave balance.
// grid (16 dtiles, 16 batches, 2 mtiles x 4 ksplits) -> 1024 working CTAs.
// CTA M=128 x N=128, 16 warps as 8m x 2n (warp 16x64); warps past nact skip.
// ---------------------------------------------------------------------------
__global__ __launch_bounds__(512, 1) void gemm_kernel(const float* __restrict__ feats) {
    const int b = blockIdx.y;
    const int mbase = (blockIdx.z >> 2) * 128;
    const int ksb = (blockIdx.z & 3) * KPER;
    const int nact = g_nact[b];
    if (mbase >= nact) return;
    const int lim = nact - mbase;       // active rows in this m-tile

    extern __shared__ char smem[];
    const uint32_t sb = smem_u32(smem);
    const int tid = threadIdx.x;
    const int lane = tid & 31, wid = tid >> 5;
    const int wm = wid & 7;             // m: wm*16
    const int wn = wid >> 3;            // n: wn*64
    const int d0 = blockIdx.x * NTILE;
    const bool wactive = (wm * 16) < lim;

    const int dcol = tid & 127;
    const int kq = tid >> 7;            // 0..3 -> k = kq*16 .. +15

    float acc[8][4];
#pragma unroll
    for (int i = 0; i < 8; i++)
#pragma unroll
        for (int r = 0; r < 4; r++) acc[i][r] = 0.0f;

    const uint32_t a_off =
        (uint32_t)((wm * 16 + (lane & 15)) * 128 + (lane >> 4) * 16);
    uint32_t b_off[4];
#pragma unroll
    for (int nb = 0; nb < 4; nb++) {
        int rowB = wn * 64 + nb * 16 + ((lane >> 4) << 3) + (lane & 7);
        b_off[nb] = (uint32_t)(rowB * 128 + ((lane >> 3) & 1) * 16);
    }

    const __nv_bfloat16* abase_g = g_Amat + (size_t)(b * MPAD + mbase) * TLEN;
    const float* fbase = feats + (size_t)b * TLEN * DDIM;

    float fst[16];

    auto issue_loads = [&](int ck, int s) {
        const int k0 = ksb + ck * KC;
        const uint32_t abase = sb + (s ? SM_A1 : SM_A0);
#pragma unroll
        for (int it = 0; it < 2; it++) {
            int idx = it * 512 + tid;
            int row = idx >> 3, seg = idx & 7;
            if (row < lim) {  // skip padding rows: garbage never stored anyway
                const void* g = abase_g + (size_t)row * TLEN + k0 + seg * 8;
                cp_async16(abase + sw128((uint32_t)(row * 128 + seg * 16)), g);
            }
        }
        cp_commit();
        const float* fp = fbase + (size_t)(k0 + kq * 16) * DDIM + d0 + dcol;
#pragma unroll
        for (int jj = 0; jj < 16; jj++) fst[jj] = fp[(size_t)jj * DDIM];
    };
    auto store_b = [&](int s) {
        const uint32_t bbase = sb + (s ? SM_B1 : SM_B0);
        uint32_t p[8];
#pragma unroll
        for (int jj = 0; jj < 8; jj++)
            p[jj] = pack_bf16x2(fst[2 * jj], fst[2 * jj + 1]);
        uint32_t o0 = (uint32_t)(dcol * 128 + kq * 32);
        sts128(bbase + sw128(o0), p[0], p[1], p[2], p[3]);
        sts128(bbase + sw128(o0 + 16), p[4], p[5], p[6], p[7]);
    };
    auto compute = [&](int s) {
        if (!wactive) return;
        const uint32_t abase = sb + (s ? SM_A1 : SM_A0);
        const uint32_t bbase = sb + (s ? SM_B1 : SM_B0);
#pragma unroll
        for (int ks = 0; ks < 4; ks++) {
            uint32_t a[4], bf[4][4];
            ldmatrix_x4(a, abase + sw128(a_off + ks * 32));
#pragma unroll
            for (int nb = 0; nb < 4; nb++)
                ldmatrix_x4(bf[nb], bbase + sw128(b_off[nb] + ks * 32));
#pragma unroll
            for (int nt = 0; nt < 8; nt++)
                mma16816(acc[nt], a,
                         bf[nt >> 1][(nt & 1) * 2], bf[nt >> 1][(nt & 1) * 2 + 1]);
        }
    };

    issue_loads(0, 0);
    cp_wait0();
    store_b(0);
    __syncthreads();

#pragma unroll 1
    for (int ck = 0; ck < NCHUNKS; ck++) {
        const int s = ck & 1;
        if (ck + 1 < NCHUNKS) issue_loads(ck + 1, s ^ 1);
        compute(s);
        if (ck + 1 < NCHUNKS) {
            store_b(s ^ 1);
            cp_wait0();
            __syncthreads();
        }
    }

    // epilogue: scatter-add compact rows to true class rows
    if (wactive) {
        const int row = lane >> 2;
        const int col = (lane & 3) * 2;
        const int j0 = mbase + wm * 16 + row;
        const int j1 = j0 + 8;
        const int c0 = (j0 < nact) ? g_clist[b * MPAD + j0] : -1;
        const int c1 = (j1 < nact) ? g_clist[b * MPAD + j1] : -1;
#pragma unroll
        for (int nt = 0; nt < 8; nt++) {
            int dd = d0 + wn * 64 + nt * 8 + col;
            if (c0 >= 0) {
                float* gp = g_sums + (size_t)c0 * DDIM + dd;
                atomicAdd(gp, acc[nt][0]);
                atomicAdd(gp + 1, acc[nt][1]);
            }
            if (c1 >= 0) {
                float* gp = g_sums + (size_t)c1 * DDIM + dd;
                atomicAdd(gp, acc[nt][2]);
                atomicAdd(gp + 1, acc[nt][3]);
            }
        }
    }
}

// ---------------------------------------------------------------------------
// Stage 3: momentum update (vectorized)
// ---------------------------------------------------------------------------
__global__ void finalize_kernel(const float4* __restrict__ proto,
                                float4* __restrict__ out) {
    int i = blockIdx.x * 256 + threadIdx.x;
    if (i >= CDIM * DDIM / 4) return;
    int c = i >> 9;
    float4 p = proto[i];
    int cnt = g_counts[c];
    const float4 s = ((const float4*)g_sums)[i];
    float inv = 0.001f / fmaxf((float)cnt, 1.0f);
    float4 r;
    r.x = 0.999f * p.x + s.x * inv;
    r.y = 0.999f * p.y + s.y * inv;
    r.z = 0.999f * p.z + s.z * inv;
    r.w = 0.999f * p.w + s.w * inv;
    out[i] = (cnt > 0) ? r : p;
}

// ---------------------------------------------------------------------------
// Launch
// ---------------------------------------------------------------------------
extern "C" void kernel_launch(void* const* d_in, const int* in_sizes, int n_in,
                              void* d_out, int out_size) {
    const float* feats = (const float*)d_in[0];
    const int* act = (const int*)d_in[1];
    const int* vid = (const int*)d_in[2];
    const float* proto = (const float*)d_in[3];
    float* out = (float*)d_out;

    cudaFuncSetAttribute(gemm_kernel, cudaFuncAttributeMaxDynamicSharedMemorySize,
                         SMEM_BYTES);

    zero_kernel<<<(SUMS_U4 + 255) / 256, 256>>>();
    prep_kernel<<<BATCH, 256>>>(vid);
    build_mask_kernel<<<BATCH * (TLEN / 64), 256>>>(act);
    gemm_kernel<<<dim3(DDIM / NTILE, BATCH, 2 * KSPLIT), 512, SMEM_BYTES>>>(feats);
    finalize_kernel<<<(CDIM * DDIM / 4 + 255) / 256, 256>>>(
        (const float4*)proto, (float4*)out);
}

// round 7
// speedup vs baseline: 1.8419x; 1.1092x over previous
#include <cuda_runtime.h>
#include <cuda_bf16.h>
#include <cstdint>

// ---------------------------------------------------------------------------
// Shapes (fixed by the bench)
// ---------------------------------------------------------------------------
#define BATCH 16
#define TLEN  2048
#define CDIM  200
#define DDIM  2048
#define MPAD  256              // compacted class rows per batch (padded)

// GEMM tiling: per-batch compacted bf16 mma.sync, hybrid full/quarter K tasks
#define KC      64             // k per smem chunk (64 bf16 = 128B SW128 row)
#define NTILE   128            // d columns per CTA
#define NTASKS  256            // 16 dtiles x 16 batches
#define NFULL   148            // full-K tasks = exactly wave 1 (one per SM)
#define NQUART  ((NTASKS - NFULL) * 4)   // 432 quarter-K tasks
#define QCHUNKS 8              // chunks per quarter task (2048/64/4)

// smem: A 2 x 16KB (128 rows x 128B), B 2 x 16KB
#define SM_A0 0
#define SM_A1 16384
#define SM_B0 32768
#define SM_B1 (32768 + 16384)
#define SMEM_BYTES 65536

// ---------------------------------------------------------------------------
// Scratch — device symbols ONLY, never passed from host (ATS shadow trap!)
// ---------------------------------------------------------------------------
__device__ __align__(128) __nv_bfloat16 g_Amat[(size_t)BATCH * MPAD * TLEN]; // 16MB
__device__ float g_sums[MPAD * DDIM];   // indexed by TRUE class (0..199)
__device__ int   g_counts[MPAD];
__device__ int   g_clist[BATCH * MPAD]; // compact j -> true class c
__device__ int   g_cmap[BATCH * MPAD];  // true class c -> compact j (or -1)
__device__ int   g_nact[BATCH];

// ---------------------------------------------------------------------------
// helpers
// ---------------------------------------------------------------------------
__device__ __forceinline__ uint32_t smem_u32(const void* p) {
    uint32_t a;
    asm("{ .reg .u64 t; cvta.to.shared.u64 t, %1; cvt.u32.u64 %0, t; }"
        : "=r"(a) : "l"(p));
    return a;
}
__device__ __forceinline__ uint32_t sw128(uint32_t off) {
    return off ^ ((off >> 3) & 0x70);
}
__device__ __forceinline__ void sts128(uint32_t a, uint32_t x, uint32_t y,
                                       uint32_t z, uint32_t w) {
    asm volatile("st.shared.v4.b32 [%0], {%1,%2,%3,%4};"
                 :: "r"(a), "r"(x), "r"(y), "r"(z), "r"(w) : "memory");
}
__device__ __forceinline__ uint32_t pack_bf16x2(float lo, float hi) {
    uint32_t r;
    asm("cvt.rn.satfinite.bf16x2.f32 %0, %1, %2;" : "=r"(r) : "f"(hi), "f"(lo));
    return r;
}
__device__ __forceinline__ void cp_async16(uint32_t saddr, const void* gaddr) {
    asm volatile("cp.async.cg.shared.global [%0], [%1], 16;"
                 :: "r"(saddr), "l"(gaddr) : "memory");
}
__device__ __forceinline__ void cp_commit() {
    asm volatile("cp.async.commit_group;" ::: "memory");
}
__device__ __forceinline__ void cp_wait0() {
    asm volatile("cp.async.wait_group 0;" ::: "memory");
}
__device__ __forceinline__ void ldmatrix_x4(uint32_t* r, uint32_t addr) {
    asm volatile("ldmatrix.sync.aligned.m8n8.x4.shared.b16 {%0,%1,%2,%3}, [%4];"
                 : "=r"(r[0]), "=r"(r[1]), "=r"(r[2]), "=r"(r[3]) : "r"(addr));
}
__device__ __forceinline__ void mma16816(float* c, const uint32_t* a,
                                         uint32_t b0, uint32_t b1) {
    asm volatile(
        "mma.sync.aligned.m16n8k16.row.col.f32.bf16.bf16.f32 "
        "{%0,%1,%2,%3}, {%4,%5,%6,%7}, {%8,%9}, {%0,%1,%2,%3};"
        : "+f"(c[0]), "+f"(c[1]), "+f"(c[2]), "+f"(c[3])
        : "r"(a[0]), "r"(a[1]), "r"(a[2]), "r"(a[3]), "r"(b0), "r"(b1));
}

// ---------------------------------------------------------------------------
// Stage 0+1a fused: blocks 0..15 do per-batch class compaction; blocks 16+
// zero sums + counts (independent outputs, both complete before consumers).
// ---------------------------------------------------------------------------
#define SUMS_U4 (MPAD * DDIM * 4 / 16)   // 131072
#define PREP_BLOCKS (BATCH + (SUMS_U4 + 255) / 256)
__global__ __launch_bounds__(256) void prep_kernel(const int* __restrict__ vid) {
    if (blockIdx.x >= BATCH) {
        int i = (blockIdx.x - BATCH) * 256 + threadIdx.x;
        const uint4 z = {0, 0, 0, 0};
        if (i < SUMS_U4) ((uint4*)g_sums)[i] = z;
        if (i < MPAD) g_counts[i] = 0;
        return;
    }
    __shared__ int warp_sums[8];
    __shared__ int warp_base[8];
    int b = blockIdx.x, tid = threadIdx.x;
    int lid = tid & 31, wid = tid >> 5;

    int flag = (tid < CDIM) ? (vid[b * CDIM + tid] != 0) : 0;
    uint32_t bal = __ballot_sync(0xFFFFFFFFu, flag);
    if (lid == 0) warp_sums[wid] = __popc(bal);
    __syncthreads();
    if (tid == 0) {
        int run = 0;
        for (int w = 0; w < 8; w++) { warp_base[w] = run; run += warp_sums[w]; }
        g_nact[b] = run;
    }
    __syncthreads();
    int j = warp_base[wid] + __popc(bal & ((1u << lid) - 1));
    if (flag) {
        g_cmap[b * MPAD + tid] = j;
        g_clist[b * MPAD + j] = tid;
    } else {
        g_cmap[b * MPAD + tid] = -1;
    }
}

// ---------------------------------------------------------------------------
// Stage 1b: compacted bf16 mask Amat[b][j][t] + per-class counts.
// Thread owns one true class (register j); block = 64 consecutive t.
// ---------------------------------------------------------------------------
__global__ __launch_bounds__(256) void build_mask_kernel(const int* __restrict__ act) {
    __shared__ __nv_bfloat16 m[CDIM][66];   // only rows < nact are written/read

    int tid = threadIdx.x;
    int b = blockIdx.x >> 5;
    int t0 = (blockIdx.x & 31) * 64;
    int nact = g_nact[b];
    int j = (tid < CDIM) ? g_cmap[b * MPAD + tid] : -1;

    const __nv_bfloat16 one = __float2bfloat16(1.0f);
    const __nv_bfloat16 zero = __float2bfloat16(0.0f);

    const int* ap = act + ((size_t)b * TLEN + t0) * CDIM + tid;
    int cnt = 0;
    if (j >= 0) {
#pragma unroll 4
        for (int r = 0; r < 64; r++) {
            bool on = ap[r * CDIM] != 0;       // coalesced across lanes
            m[j][r] = on ? one : zero;
            cnt += on;
        }
        if (cnt) atomicAdd(&g_counts[tid], cnt);
    }
    __syncthreads();

    int lid = tid & 31, wid = tid >> 5;
    for (int jj = wid; jj < nact; jj += 8) {
        uint32_t v = *(const uint32_t*)&m[jj][2 * lid];
        *(uint32_t*)((char*)g_Amat +
                     ((size_t)(b * MPAD + jj) * TLEN + t0 + 2 * lid) * 2) = v;
    }
}

// ---------------------------------------------------------------------------
// Stage 2: per-batch compacted bf16 GEMM, hybrid scheduling:
//   bid.x <  148            : full-K task    (task = bid.x,          32 chunks)
//   bid.x >= 148            : quarter-K task (task = 148+(r>>2), q=r&3, 8 chunks)
// Fulls fill wave 1 exactly (1/SM); quarters backfill via work-stealing ->
// makespan ~1.75T instead of 2T, with ramp/atomics only on 42% of the work.
// CTA M=128 x N=128, 16 warps as 8m x 2n; warps past nact skip compute.
// gridDim.y=2 covers the (rare) nact>128 second m-tile; those exit instantly.
// ---------------------------------------------------------------------------
__global__ __launch_bounds__(512, 1) void gemm_kernel(const float* __restrict__ feats) {
    int task, ck0, nch;
    if (blockIdx.x < NFULL) {
        task = blockIdx.x;           ck0 = 0;                         nch = 32;
    } else {
        int r = blockIdx.x - NFULL;
        task = NFULL + (r >> 2);     ck0 = (r & 3) * QCHUNKS;         nch = QCHUNKS;
    }
    const int b = task & 15;
    const int d0 = (task >> 4) * NTILE;
    const int mbase = blockIdx.y * 128;
    const int nact = g_nact[b];
    if (mbase >= nact) return;
    const int lim = nact - mbase;       // active rows in this m-tile

    extern __shared__ char smem[];
    const uint32_t sb = smem_u32(smem);
    const int tid = threadIdx.x;
    const int lane = tid & 31, wid = tid >> 5;
    const int wm = wid & 7;             // m: wm*16
    const int wn = wid >> 3;            // n: wn*64
    const bool wactive = (wm * 16) < lim;

    const int dcol = tid & 127;
    const int kq = tid >> 7;            // 0..3 -> k = kq*16 .. +15

    float acc[8][4];
#pragma unroll
    for (int i = 0; i < 8; i++)
#pragma unroll
        for (int r = 0; r < 4; r++) acc[i][r] = 0.0f;

    const uint32_t a_off =
        (uint32_t)((wm * 16 + (lane & 15)) * 128 + (lane >> 4) * 16);
    uint32_t b_off[4];
#pragma unroll
    for (int nb = 0; nb < 4; nb++) {
        int rowB = wn * 64 + nb * 16 + ((lane >> 4) << 3) + (lane & 7);
        b_off[nb] = (uint32_t)(rowB * 128 + ((lane >> 3) & 1) * 16);
    }

    const __nv_bfloat16* abase_g = g_Amat + (size_t)(b * MPAD + mbase) * TLEN;
    const float* fbase = feats + (size_t)b * TLEN * DDIM;

    float fst[16];

    auto issue_loads = [&](int ck, int s) {
        const int k0 = ck * KC;
        const uint32_t abase = sb + (s ? SM_A1 : SM_A0);
#pragma unroll
        for (int it = 0; it < 2; it++) {
            int idx = it * 512 + tid;
            int row = idx >> 3, seg = idx & 7;
            if (row < lim) {  // padding rows: garbage never consumed anyway
                const void* g = abase_g + (size_t)row * TLEN + k0 + seg * 8;
                cp_async16(abase + sw128((uint32_t)(row * 128 + seg * 16)), g);
            }
        }
        cp_commit();
        const float* fp = fbase + (size_t)(k0 + kq * 16) * DDIM + d0 + dcol;
#pragma unroll
        for (int jj = 0; jj < 16; jj++) fst[jj] = fp[(size_t)jj * DDIM];
    };
    auto store_b = [&](int s) {
        const uint32_t bbase = sb + (s ? SM_B1 : SM_B0);
        uint32_t p[8];
#pragma unroll
        for (int jj = 0; jj < 8; jj++)
            p[jj] = pack_bf16x2(fst[2 * jj], fst[2 * jj + 1]);
        uint32_t o0 = (uint32_t)(dcol * 128 + kq * 32);
        sts128(bbase + sw128(o0), p[0], p[1], p[2], p[3]);
        sts128(bbase + sw128(o0 + 16), p[4], p[5], p[6], p[7]);
    };
    auto compute = [&](int s) {
        if (!wactive) return;
        const uint32_t abase = sb + (s ? SM_A1 : SM_A0);
        const uint32_t bbase = sb + (s ? SM_B1 : SM_B0);
#pragma unroll
        for (int ks = 0; ks < 4; ks++) {
            uint32_t a[4], bf[4][4];
            ldmatrix_x4(a, abase + sw128(a_off + ks * 32));
#pragma unroll
            for (int nb = 0; nb < 4; nb++)
                ldmatrix_x4(bf[nb], bbase + sw128(b_off[nb] + ks * 32));
#pragma unroll
            for (int nt = 0; nt < 8; nt++)
                mma16816(acc[nt], a,
                         bf[nt >> 1][(nt & 1) * 2], bf[nt >> 1][(nt & 1) * 2 + 1]);
        }
    };

    issue_loads(ck0, 0);
    cp_wait0();
    store_b(0);
    __syncthreads();

#pragma unroll 1
    for (int i = 0; i < nch; i++) {
        const int s = i & 1;
        if (i + 1 < nch) issue_loads(ck0 + i + 1, s ^ 1);
        compute(s);
        if (i + 1 < nch) {
            store_b(s ^ 1);
            cp_wait0();
            __syncthreads();
        }
    }

    // epilogue: scatter-add compact rows to true class rows
    if (wactive) {
        const int row = lane >> 2;
        const int col = (lane & 3) * 2;
        const int j0 = mbase + wm * 16 + row;
        const int j1 = j0 + 8;
        const int c0 = (j0 < nact) ? g_clist[b * MPAD + j0] : -1;
        const int c1 = (j1 < nact) ? g_clist[b * MPAD + j1] : -1;
#pragma unroll
        for (int nt = 0; nt < 8; nt++) {
            int dd = d0 + wn * 64 + nt * 8 + col;
            if (c0 >= 0) {
                float* gp = g_sums + (size_t)c0 * DDIM + dd;
                atomicAdd(gp, acc[nt][0]);
                atomicAdd(gp + 1, acc[nt][1]);
            }
            if (c1 >= 0) {
                float* gp = g_sums + (size_t)c1 * DDIM + dd;
                atomicAdd(gp, acc[nt][2]);
                atomicAdd(gp + 1, acc[nt][3]);
            }
        }
    }
}

// ---------------------------------------------------------------------------
// Stage 3: momentum update (vectorized)
// ---------------------------------------------------------------------------
__global__ void finalize_kernel(const float4* __restrict__ proto,
                                float4* __restrict__ out) {
    int i = blockIdx.x * 256 + threadIdx.x;
    if (i >= CDIM * DDIM / 4) return;
    int c = i >> 9;
    float4 p = proto[i];
    int cnt = g_counts[c];
    const float4 s = ((const float4*)g_sums)[i];
    float inv = 0.001f / fmaxf((float)cnt, 1.0f);
    float4 r;
    r.x = 0.999f * p.x + s.x * inv;
    r.y = 0.999f * p.y + s.y * inv;
    r.z = 0.999f * p.z + s.z * inv;
    r.w = 0.999f * p.w + s.w * inv;
    out[i] = (cnt > 0) ? r : p;
}

// ---------------------------------------------------------------------------
// Launch
// ---------------------------------------------------------------------------
extern "C" void kernel_launch(void* const* d_in, const int* in_sizes, int n_in,
                              void* d_out, int out_size) {
    const float* feats = (const float*)d_in[0];
    const int* act = (const int*)d_in[1];
    const int* vid = (const int*)d_in[2];
    const float* proto = (const float*)d_in[3];
    float* out = (float*)d_out;

    cudaFuncSetAttribute(gemm_kernel, cudaFuncAttributeMaxDynamicSharedMemorySize,
                         SMEM_BYTES);

    prep_kernel<<<PREP_BLOCKS, 256>>>(vid);
    build_mask_kernel<<<BATCH * (TLEN / 64), 256>>>(act);
    gemm_kernel<<<dim3(NFULL + NQUART, 2), 512, SMEM_BYTES>>>(feats);
    finalize_kernel<<<(CDIM * DDIM / 4 + 255) / 256, 256>>>(
        (const float4*)proto, (float4*)out);
}